// round 12
// baseline (speedup 1.0000x reference)
#include <cuda_runtime.h>
#include <cuda_bf16.h>

#define BB 4
#define CF 256
#define CC 64
#define HH 128
#define WW 128
#define HW (HH * WW)
#define CP 80
#define PH 64
#define PW 64
#define KS 5
#define KK 25

typedef unsigned long long ull;
typedef unsigned int u32;

// scratch (no allocations allowed)
__device__ __nv_bfloat16 g_guide_px[BB * HW * CC];   // 8.4 MB, [b][pixel][ch]
__device__ float g_mask[BB * KK * HW];               // 6.5 MB

__device__ __forceinline__ int refl(int v, int n) {
    v = (v < 0) ? -v : v;
    v = (v >= n) ? (2 * n - 2 - v) : v;
    return v;
}

__device__ __forceinline__ void ffma2(ull& d, ull a, ull b) {
    asm("fma.rn.f32x2 %0, %1, %2, %3;" : "=l"(d) : "l"(a), "l"(b), "l"(d));
}
__device__ __forceinline__ ull pack2(float x, float y) {
    ull r;
    asm("mov.b64 %0, {%1, %2};" : "=l"(r) : "f"(x), "f"(y));
    return r;
}
__device__ __forceinline__ void unpack2(ull v, float& x, float& y) {
    asm("mov.b64 {%0, %1}, %2;" : "=f"(x), "=f"(y) : "l"(v));
}

__device__ __forceinline__ void mma_bf16(float& c0, float& c1, float& c2, float& c3,
                                         u32 a0, u32 a1, u32 a2, u32 a3,
                                         u32 b0, u32 b1) {
    asm volatile(
        "mma.sync.aligned.m16n8k16.row.col.f32.bf16.bf16.f32 "
        "{%0,%1,%2,%3}, {%4,%5,%6,%7}, {%8,%9}, {%0,%1,%2,%3};"
        : "+f"(c0), "+f"(c1), "+f"(c2), "+f"(c3)
        : "r"(a0), "r"(a1), "r"(a2), "r"(a3), "r"(b0), "r"(b1));
}

// 128B-row XOR swizzle (16B chunks)
__device__ __forceinline__ int off128(int r, int kb) {
    return r * 128 + ((((kb >> 4) ^ (r & 7)) << 4) | (kb & 15));
}

// ---------------------------------------------------------------------------
// Kernel 1 (HMMA v3): 64x64 N-tile for occupancy (3 CTAs/SM target).
// Fragment addressing identical to verified R10; only tile width changes.
// ---------------------------------------------------------------------------
#define CMP_DYN (32768 + 2 * 8192)

__device__ __forceinline__ int a_off(int row, int kbyte) {
    int c = kbyte >> 4;
    return row * 512 + (((c ^ (row & 7)) << 4) | (kbyte & 15));
}
__device__ __forceinline__ int b_off(int n, int kbyte) {
    int c = kbyte >> 4;
    return n * 128 + (((c ^ (n & 7)) << 4) | (kbyte & 15));
}

__device__ __forceinline__ u32 bf2(float x, float y) {
    __nv_bfloat162 v = __floats2bfloat162_rn(x, y);
    return *(u32*)&v;
}

__global__ void __launch_bounds__(256, 3)
compress_mma_kernel(const float* __restrict__ feat,
                    const float* __restrict__ wc,
                    const float* __restrict__ bc) {
    extern __shared__ char dyn[];
    char* smA = dyn;                       // 32KB
    char* smB[2] = { dyn + 32768, dyn + 32768 + 8192 };

    int tid = threadIdx.x;
    int wid = tid >> 5;
    int lane = tid & 31;
    int g = lane >> 2;
    int t = lane & 3;
    int warpM = wid >> 2;    // 0..1
    int warpN = wid & 3;     // 0..3 (16 cols each)
    int b  = blockIdx.y;
    int n0 = blockIdx.x * 64;

    // ---- stage A (64x256 bf16, swizzled; wc is L2-resident) ----
    for (int q = tid; q < 64 * 128; q += 256) {
        int m = q >> 7, kp = q & 127;
        float2 w = *(const float2*)&wc[m * CF + 2 * kp];
        *(__nv_bfloat162*)(smA + a_off(m, kp * 4)) = __floats2bfloat162_rn(w.x, w.y);
    }

    const float* fbase = feat + (size_t)b * CF * HW + n0;
    int n4 = tid & 15;        // 16 n-quads (4 cols each)
    int kq = tid >> 4;        // 16 k-quads (4 k's each) within chunk

    // ---- stage chunk 0 ----
    {
        char* buf = smB[0];
        const float* p = fbase + (size_t)(4 * kq) * HW + 4 * n4;
        float4 v0 = *(const float4*)p;
        float4 v1 = *(const float4*)(p + HW);
        float4 v2 = *(const float4*)(p + 2 * HW);
        float4 v3 = *(const float4*)(p + 3 * HW);
        float a0[4] = {v0.x, v0.y, v0.z, v0.w};
        float a1[4] = {v1.x, v1.y, v1.z, v1.w};
        float a2[4] = {v2.x, v2.y, v2.z, v2.w};
        float a3[4] = {v3.x, v3.y, v3.z, v3.w};
#pragma unroll
        for (int j = 0; j < 4; j++) {
            uint2 pr = make_uint2(bf2(a0[j], a1[j]), bf2(a2[j], a3[j]));
            *(uint2*)(buf + b_off(4 * n4 + j, 8 * kq)) = pr;
        }
    }
    __syncthreads();

    float acc[2][2][4];
#pragma unroll
    for (int mm = 0; mm < 2; mm++)
#pragma unroll
        for (int nf = 0; nf < 2; nf++)
#pragma unroll
            for (int i = 0; i < 4; i++) acc[mm][nf][i] = 0.f;

    float4 st[4];

    for (int c = 0; c < 4; c++) {
        // issue next chunk's loads early
        if (c < 3) {
            const float* p = fbase + (size_t)((c + 1) * 64 + 4 * kq) * HW + 4 * n4;
            st[0] = *(const float4*)p;
            st[1] = *(const float4*)(p + HW);
            st[2] = *(const float4*)(p + 2 * HW);
            st[3] = *(const float4*)(p + 3 * HW);
        }

        // compute chunk c
        char* buf = smB[c & 1];
#pragma unroll
        for (int ks = 0; ks < 4; ks++) {
            int kstep = c * 4 + ks;
            u32 a[2][4];
#pragma unroll
            for (int mm = 0; mm < 2; mm++) {
                int row  = warpM * 32 + mm * 16 + g;
                int row8 = row + 8;
                int kb0 = kstep * 32 + 4 * t;
                int kb1 = kb0 + 16;
                a[mm][0] = *(const u32*)(smA + a_off(row,  kb0));
                a[mm][1] = *(const u32*)(smA + a_off(row8, kb0));
                a[mm][2] = *(const u32*)(smA + a_off(row,  kb1));
                a[mm][3] = *(const u32*)(smA + a_off(row8, kb1));
            }
            u32 bf[2][2];
#pragma unroll
            for (int nf = 0; nf < 2; nf++) {
                int n = warpN * 16 + nf * 8 + g;
                int kb0 = ks * 32 + 4 * t;
                bf[nf][0] = *(const u32*)(buf + b_off(n, kb0));
                bf[nf][1] = *(const u32*)(buf + b_off(n, kb0 + 16));
            }
#pragma unroll
            for (int mm = 0; mm < 2; mm++)
#pragma unroll
                for (int nf = 0; nf < 2; nf++)
                    mma_bf16(acc[mm][nf][0], acc[mm][nf][1],
                             acc[mm][nf][2], acc[mm][nf][3],
                             a[mm][0], a[mm][1], a[mm][2], a[mm][3],
                             bf[nf][0], bf[nf][1]);
        }

        // store staged chunk c+1
        if (c < 3) {
            char* nb = smB[(c + 1) & 1];
            float a0[4] = {st[0].x, st[0].y, st[0].z, st[0].w};
            float a1[4] = {st[1].x, st[1].y, st[1].z, st[1].w};
            float a2[4] = {st[2].x, st[2].y, st[2].z, st[2].w};
            float a3[4] = {st[3].x, st[3].y, st[3].z, st[3].w};
#pragma unroll
            for (int j = 0; j < 4; j++) {
                uint2 pr = make_uint2(bf2(a0[j], a1[j]), bf2(a2[j], a3[j]));
                *(uint2*)(nb + b_off(4 * n4 + j, 8 * kq)) = pr;
            }
        }
        __syncthreads();
    }

    // ---- epilogue: transpose 64px x 64ch to pixel-major bf16 ----
    __nv_bfloat16* T = (__nv_bfloat16*)(dyn + 32768);   // [64 px][68]
#pragma unroll
    for (int mm = 0; mm < 2; mm++) {
        int row  = warpM * 32 + mm * 16 + g;
        float bias0 = bc[row];
        float bias8 = bc[row + 8];
#pragma unroll
        for (int nf = 0; nf < 2; nf++) {
            int ncol = warpN * 16 + nf * 8 + 2 * t;
            T[ncol * 68 + row]           = __float2bfloat16(acc[mm][nf][0] + bias0);
            T[(ncol + 1) * 68 + row]     = __float2bfloat16(acc[mm][nf][1] + bias0);
            T[ncol * 68 + row + 8]       = __float2bfloat16(acc[mm][nf][2] + bias8);
            T[(ncol + 1) * 68 + row + 8] = __float2bfloat16(acc[mm][nf][3] + bias8);
        }
    }
    __syncthreads();

    u32* gpx = (u32*)g_guide_px + ((size_t)b * HW + n0) * 32;
#pragma unroll
    for (int r = 0; r < 8; r++) {
        int idx = tid + r * 256;        // 0..2047
        int n  = idx >> 5;              // 0..63
        int m2 = idx & 31;
        gpx[n * 32 + m2] = *(u32*)&T[n * 68 + 2 * m2];
    }
}

// ---------------------------------------------------------------------------
// Kernel 2 (HMMA, verified R10): 3x3 conv + bias + softmax(25)
// ---------------------------------------------------------------------------
#define CV_AW_OFF 0
#define CV_HT_OFF 36864
#define CV_DS_OFF (36864 + 26112)
#define CV_DYN    (36864 + 26112 + 128 * 37 * 4)

__global__ void __launch_bounds__(256)
conv_softmax_mma_kernel(const float* __restrict__ we,
                        const float* __restrict__ be) {
    extern __shared__ char dyn[];
    char*  smAw = dyn + CV_AW_OFF;
    char*  smHt = dyn + CV_HT_OFF;
    float* smDs = (float*)(dyn + CV_DS_OFF);

    int tid = threadIdx.x;
    int wid = tid >> 5;
    int lane = tid & 31;
    int g = lane >> 2;
    int t = lane & 3;
    int b  = blockIdx.z;
    int x0 = blockIdx.x * 32;
    int y0 = blockIdx.y * 4;

    for (int i = tid; i < 9 * 32 * 32; i += 256) {
        int tap = i >> 10;
        int rem = i & 1023;
        int o  = rem >> 5;
        int cp = rem & 31;
        float w0 = 0.f, w1 = 0.f;
        if (o < KK) {
            w0 = we[(o * CC + 2 * cp) * 9 + tap];
            w1 = we[(o * CC + 2 * cp + 1) * 9 + tap];
        }
        *(u32*)(smAw + tap * 4096 + off128(o, cp * 4)) = bf2(w0, w1);
    }

    const u32* gpx = (const u32*)g_guide_px + (size_t)b * HW * 32;
    for (int i = tid; i < 204 * 32; i += 256) {
        int pos = i >> 5;
        int cp  = i & 31;
        int r   = pos / 34;
        int cxl = pos - r * 34;
        int gy = y0 + r - 1;
        int gx = x0 + cxl - 1;
        u32 v = 0u;
        if (gy >= 0 && gy < HH && gx >= 0 && gx < WW)
            v = gpx[(gy * WW + gx) * 32 + cp];
        *(u32*)(smHt + off128(pos, cp * 4)) = v;
    }
    __syncthreads();

    int nbase = wid * 16;
    float acc[2][2][4];
#pragma unroll
    for (int mm = 0; mm < 2; mm++)
#pragma unroll
        for (int nf = 0; nf < 2; nf++)
#pragma unroll
            for (int i = 0; i < 4; i++) acc[mm][nf][i] = 0.f;

#pragma unroll
    for (int tap = 0; tap < 9; tap++) {
        int ty = tap / 3, tx = tap - 3 * ty;
        const char* aw = smAw + tap * 4096;
#pragma unroll
        for (int ks = 0; ks < 4; ks++) {
            int kb0 = ks * 32 + 4 * t;
            int kb1 = kb0 + 16;
            u32 a[2][4];
#pragma unroll
            for (int mm = 0; mm < 2; mm++) {
                int row = mm * 16 + g;
                a[mm][0] = *(const u32*)(aw + off128(row,     kb0));
                a[mm][1] = *(const u32*)(aw + off128(row + 8, kb0));
                a[mm][2] = *(const u32*)(aw + off128(row,     kb1));
                a[mm][3] = *(const u32*)(aw + off128(row + 8, kb1));
            }
            u32 bf[2][2];
#pragma unroll
            for (int nf = 0; nf < 2; nf++) {
                int n = nbase + nf * 8 + g;
                int px = n & 31;
                int py = n >> 5;
                int pos = (py + ty) * 34 + (px + tx);
                bf[nf][0] = *(const u32*)(smHt + off128(pos, kb0));
                bf[nf][1] = *(const u32*)(smHt + off128(pos, kb1));
            }
#pragma unroll
            for (int mm = 0; mm < 2; mm++)
#pragma unroll
                for (int nf = 0; nf < 2; nf++)
                    mma_bf16(acc[mm][nf][0], acc[mm][nf][1],
                             acc[mm][nf][2], acc[mm][nf][3],
                             a[mm][0], a[mm][1], a[mm][2], a[mm][3],
                             bf[nf][0], bf[nf][1]);
        }
    }

#pragma unroll
    for (int mm = 0; mm < 2; mm++) {
        int row = mm * 16 + g;
#pragma unroll
        for (int nf = 0; nf < 2; nf++) {
            int n = nbase + nf * 8 + 2 * t;
            smDs[n * 37 + row]           = acc[mm][nf][0];
            smDs[(n + 1) * 37 + row]     = acc[mm][nf][1];
            smDs[n * 37 + row + 8]       = acc[mm][nf][2];
            smDs[(n + 1) * 37 + row + 8] = acc[mm][nf][3];
        }
    }
    __syncthreads();

    if (tid < 128) {
        int n = tid;
        int px = n & 31;
        int py = n >> 5;
        float a[KK];
        float m = -1e30f;
#pragma unroll
        for (int o = 0; o < KK; o++) {
            a[o] = smDs[n * 37 + o] + be[o];
            m = fmaxf(m, a[o]);
        }
        float s = 0.f;
#pragma unroll
        for (int o = 0; o < KK; o++) {
            a[o] = __expf(a[o] - m);
            s += a[o];
        }
        float inv = 1.f / s;
        float* mb = g_mask + (size_t)b * KK * HW + (y0 + py) * WW + (x0 + px);
#pragma unroll
        for (int o = 0; o < KK; o++) mb[(size_t)o * HW] = a[o] * inv;
    }
}

// ---------------------------------------------------------------------------
// Kernel 3 (v4, verified R11): CARAFE, double-buffered + pipelined.
// ---------------------------------------------------------------------------
#define CCH 8
#define CSPLIT 2
#define CPB (CP / CSPLIT)
#define NCHUNK (CPB / CCH)

__global__ void __launch_bounds__(256)
carafe_kernel(const float* __restrict__ pred,
              float* __restrict__ out) {
    __shared__ float ps[2][CCH][8][36];

    int zb = blockIdx.z;
    int b  = zb & (BB - 1);
    int cs = zb >> 2;
    int X0 = blockIdx.x * 64;
    int Y0 = blockIdx.y * 8;
    int lx = threadIdx.x & 31;
    int ly = threadIdx.x >> 5;
    int tid = threadIdx.x;
    int X = X0 + 2 * lx;
    int Y = Y0 + ly;

    ull m2[KK];
    const float* mb = g_mask + (size_t)b * KK * HW + Y * WW + X;
#pragma unroll
    for (int o = 0; o < KK; o++) {
        float2 mv = *(const float2*)&mb[(size_t)o * HW];
        m2[o] = pack2(mv.x, mv.y);
    }

    int py = ly >> 1;
    int px = lx;
    int yin0 = Y0 / 2 - 2;
    int xin0 = X0 / 2 - 2;

    int goff[9];
    int sch[9], sr[9], sc[9];
#pragma unroll
    for (int u = 0; u < 9; u++) {
        int i = u * 256 + tid;
        int ch = i / 288;
        int r  = (i / 36) % 8;
        int c  = i % 36;
        sch[u] = ch; sr[u] = r; sc[u] = c;
        goff[u] = ch * (PH * PW) + refl(yin0 + r, PH) * PW + refl(xin0 + c, PW);
    }

    const float* pb = pred + (size_t)b * CP * PH * PW + (size_t)cs * CPB * PH * PW;
    float* ob = out + (size_t)b * CP * HW + (size_t)cs * CPB * HW + Y * WW + X;

    {
        float r[9];
#pragma unroll
        for (int u = 0; u < 9; u++) r[u] = pb[goff[u]];
#pragma unroll
        for (int u = 0; u < 9; u++) ps[0][sch[u]][sr[u]][sc[u]] = r[u];
    }
    __syncthreads();

    float rnext[9];
    for (int c = 0; c < NCHUNK; c++) {
        if (c < NCHUNK - 1) {
            const float* pn = pb + (size_t)(c + 1) * CCH * PH * PW;
#pragma unroll
            for (int u = 0; u < 9; u++) rnext[u] = pn[goff[u]];
        }

        const float (*cur)[8][36] = ps[c & 1];
        int cp0 = c * CCH;
#pragma unroll
        for (int ch = 0; ch < CCH; ch++) {
            ull s2 = 0ULL;
#pragma unroll
            for (int i = 0; i < 5; i++)
#pragma unroll
                for (int j = 0; j < 5; j++) {
                    float p = cur[ch][py + i][px + j];
                    ffma2(s2, pack2(p, p), m2[i * 5 + j]);
                }
            float r0, r1;
            unpack2(s2, r0, r1);
            *(float2*)&ob[(size_t)(cp0 + ch) * HW] = make_float2(r0, r1);
        }

        if (c < NCHUNK - 1) {
#pragma unroll
            for (int u = 0; u < 9; u++)
                ps[(c + 1) & 1][sch[u]][sr[u]][sc[u]] = rnext[u];
        }
        __syncthreads();
    }
}

extern "C" void kernel_launch(void* const* d_in, const int* in_sizes, int n_in,
                              void* d_out, int out_size) {
    const float* pred = (const float*)d_in[0];
    const float* feat = (const float*)d_in[1];
    const float* wc   = (const float*)d_in[2];
    const float* bc   = (const float*)d_in[3];
    const float* we   = (const float*)d_in[4];
    const float* be   = (const float*)d_in[5];
    float* out = (float*)d_out;

    cudaFuncSetAttribute(compress_mma_kernel,
                         cudaFuncAttributeMaxDynamicSharedMemorySize, CMP_DYN);
    cudaFuncSetAttribute(conv_softmax_mma_kernel,
                         cudaFuncAttributeMaxDynamicSharedMemorySize, CV_DYN);

    compress_mma_kernel<<<dim3(HW / 64, BB), 256, CMP_DYN>>>(feat, wc, bc);
    conv_softmax_mma_kernel<<<dim3(WW / 32, HH / 4, BB), 256, CV_DYN>>>(we, be);
    carafe_kernel<<<dim3(WW / 64, HH / 8, BB * CSPLIT), 256>>>(pred, out);
}

// round 13
// speedup vs baseline: 1.1095x; 1.1095x over previous
#include <cuda_runtime.h>
#include <cuda_bf16.h>

#define BB 4
#define CF 256
#define CC 64
#define HH 128
#define WW 128
#define HW (HH * WW)
#define CP 80
#define PH 64
#define PW 64
#define KS 5
#define KK 25

typedef unsigned long long ull;
typedef unsigned int u32;

// scratch (no allocations allowed)
__device__ __nv_bfloat16 g_guide_px[BB * HW * CC];   // 8.4 MB, [b][pixel][ch]
__device__ float g_mask[BB * KK * HW];               // 6.5 MB

__device__ __forceinline__ int refl(int v, int n) {
    v = (v < 0) ? -v : v;
    v = (v >= n) ? (2 * n - 2 - v) : v;
    return v;
}

__device__ __forceinline__ void ffma2(ull& d, ull a, ull b) {
    asm("fma.rn.f32x2 %0, %1, %2, %3;" : "=l"(d) : "l"(a), "l"(b), "l"(d));
}
__device__ __forceinline__ ull pack2(float x, float y) {
    ull r;
    asm("mov.b64 %0, {%1, %2};" : "=l"(r) : "f"(x), "f"(y));
    return r;
}
__device__ __forceinline__ void unpack2(ull v, float& x, float& y) {
    asm("mov.b64 {%0, %1}, %2;" : "=f"(x), "=f"(y) : "l"(v));
}

__device__ __forceinline__ void mma_bf16(float& c0, float& c1, float& c2, float& c3,
                                         u32 a0, u32 a1, u32 a2, u32 a3,
                                         u32 b0, u32 b1) {
    asm volatile(
        "mma.sync.aligned.m16n8k16.row.col.f32.bf16.bf16.f32 "
        "{%0,%1,%2,%3}, {%4,%5,%6,%7}, {%8,%9}, {%0,%1,%2,%3};"
        : "+f"(c0), "+f"(c1), "+f"(c2), "+f"(c3)
        : "r"(a0), "r"(a1), "r"(a2), "r"(a3), "r"(b0), "r"(b1));
}

__device__ __forceinline__ void ldsm4(u32& d0, u32& d1, u32& d2, u32& d3, u32 addr) {
    asm volatile("ldmatrix.sync.aligned.m8n8.x4.shared.b16 {%0,%1,%2,%3}, [%4];"
                 : "=r"(d0), "=r"(d1), "=r"(d2), "=r"(d3) : "r"(addr));
}

__device__ __forceinline__ u32 smem_u32(const void* p) {
    u32 a;
    asm("{ .reg .u64 t; cvta.to.shared.u64 t, %1; cvt.u32.u64 %0, t; }"
        : "=r"(a) : "l"(p));
    return a;
}

// 128B-row XOR swizzle (16B chunks)
__device__ __forceinline__ int off128(int r, int kb) {
    return r * 128 + ((((kb >> 4) ^ (r & 7)) << 4) | (kb & 15));
}

// ---------------------------------------------------------------------------
// Kernel 1 (HMMA v4): R11 tile shape (64x128) + ldmatrix fragment loads.
// ---------------------------------------------------------------------------
#define CMP_DYN (32768 + 2 * 16384)

__device__ __forceinline__ int a_off(int row, int kbyte) {
    int c = kbyte >> 4;
    return row * 512 + (((c ^ (row & 7)) << 4) | (kbyte & 15));
}
__device__ __forceinline__ int b_off(int n, int kbyte) {
    int c = kbyte >> 4;
    return n * 128 + (((c ^ (n & 7)) << 4) | (kbyte & 15));
}

__device__ __forceinline__ u32 bf2(float x, float y) {
    __nv_bfloat162 v = __floats2bfloat162_rn(x, y);
    return *(u32*)&v;
}

__global__ void __launch_bounds__(256)
compress_mma_kernel(const float* __restrict__ feat,
                    const float* __restrict__ wc,
                    const float* __restrict__ bc) {
    extern __shared__ char dyn[];
    char* smA = dyn;
    char* smB[2] = { dyn + 32768, dyn + 32768 + 16384 };
    u32 smA_u = smem_u32(smA);
    u32 smB_u[2] = { smem_u32(smB[0]), smem_u32(smB[1]) };

    int tid = threadIdx.x;
    int wid = tid >> 5;
    int lane = tid & 31;
    int warpM = wid >> 2;
    int warpN = wid & 3;
    int b  = blockIdx.y;
    int n0 = blockIdx.x * 128;

    // ldmatrix lane addressing (verified-equivalent to scalar layout):
    int mi = lane >> 3;            // matrix index 0..3
    int r8 = lane & 7;             // row within 8x8
    // A: mi&1 -> +8 rows, mi>>1 -> +16B k-chunk
    int aRow = warpM * 32 + ((mi & 1) << 3) + r8;
    u32 aAddr0 = smA_u + aRow * 512;          // mm=0 base
    u32 aAddr1 = aAddr0 + 16 * 512;           // mm=1 base (row&7 unchanged)
    int aCo = mi >> 1;
    // B: mi>>1 -> +8 n-rows, mi&1 -> +16B k-chunk
    int bRow0 = warpN * 32 + ((mi >> 1) << 3) + r8;   // group 0 (nf 0,1)
    int bCo = mi & 1;

    // ---- stage A (64x256 bf16, swizzled) ----
    for (int q = tid; q < 64 * 128; q += 256) {
        int m = q >> 7, kp = q & 127;
        float2 w = *(const float2*)&wc[m * CF + 2 * kp];
        *(__nv_bfloat162*)(smA + a_off(m, kp * 4)) = __floats2bfloat162_rn(w.x, w.y);
    }

    const float* fbase = feat + (size_t)b * CF * HW + n0;
    int n4 = tid & 31;
    int kq0 = tid >> 5;

    {
        char* buf = smB[0];
#pragma unroll
        for (int u = 0; u < 2; u++) {
            int kq = kq0 + u * 8;
            const float* p = fbase + (size_t)(4 * kq) * HW + 4 * n4;
            float4 v0 = *(const float4*)p;
            float4 v1 = *(const float4*)(p + HW);
            float4 v2 = *(const float4*)(p + 2 * HW);
            float4 v3 = *(const float4*)(p + 3 * HW);
            float a0[4] = {v0.x, v0.y, v0.z, v0.w};
            float a1[4] = {v1.x, v1.y, v1.z, v1.w};
            float a2[4] = {v2.x, v2.y, v2.z, v2.w};
            float a3[4] = {v3.x, v3.y, v3.z, v3.w};
#pragma unroll
            for (int j = 0; j < 4; j++) {
                uint2 pr = make_uint2(bf2(a0[j], a1[j]), bf2(a2[j], a3[j]));
                *(uint2*)(buf + b_off(4 * n4 + j, 8 * kq)) = pr;
            }
        }
    }
    __syncthreads();

    float acc[2][4][4];
#pragma unroll
    for (int mm = 0; mm < 2; mm++)
#pragma unroll
        for (int nf = 0; nf < 4; nf++)
#pragma unroll
            for (int i = 0; i < 4; i++) acc[mm][nf][i] = 0.f;

    float4 st[8];

    for (int c = 0; c < 4; c++) {
        if (c < 3) {
            const float* fc = fbase + (size_t)((c + 1) * 64) * HW;
#pragma unroll
            for (int u = 0; u < 2; u++) {
                int kq = kq0 + u * 8;
                const float* p = fc + (size_t)(4 * kq) * HW + 4 * n4;
                st[u * 4 + 0] = *(const float4*)p;
                st[u * 4 + 1] = *(const float4*)(p + HW);
                st[u * 4 + 2] = *(const float4*)(p + 2 * HW);
                st[u * 4 + 3] = *(const float4*)(p + 3 * HW);
            }
        }

        u32 bufU = smB_u[c & 1];
#pragma unroll
        for (int ks = 0; ks < 4; ks++) {
            int kstep = c * 4 + ks;
            // A frags: 2 ldmatrix.x4 (chunk idx within A row = kstep*2 + aCo)
            u32 sA = (u32)(((kstep * 2 + aCo) ^ r8) << 4);
            u32 a0_[4], a1_[4];
            ldsm4(a0_[0], a0_[1], a0_[2], a0_[3], aAddr0 + sA);
            ldsm4(a1_[0], a1_[1], a1_[2], a1_[3], aAddr1 + sA);
            // B frags: 2 ldmatrix.x4 (chunk idx within B row = ks*2 + bCo)
            u32 sB = (u32)(((ks * 2 + bCo) ^ r8) << 4);
            u32 b01[4], b23[4];
            ldsm4(b01[0], b01[1], b01[2], b01[3], bufU + bRow0 * 128 + sB);
            ldsm4(b23[0], b23[1], b23[2], b23[3], bufU + (bRow0 + 16) * 128 + sB);

            u32 bf[4][2] = { {b01[0], b01[1]}, {b01[2], b01[3]},
                             {b23[0], b23[1]}, {b23[2], b23[3]} };
#pragma unroll
            for (int nf = 0; nf < 4; nf++) {
                mma_bf16(acc[0][nf][0], acc[0][nf][1], acc[0][nf][2], acc[0][nf][3],
                         a0_[0], a0_[1], a0_[2], a0_[3], bf[nf][0], bf[nf][1]);
                mma_bf16(acc[1][nf][0], acc[1][nf][1], acc[1][nf][2], acc[1][nf][3],
                         a1_[0], a1_[1], a1_[2], a1_[3], bf[nf][0], bf[nf][1]);
            }
        }

        if (c < 3) {
            char* nb = smB[(c + 1) & 1];
#pragma unroll
            for (int u = 0; u < 2; u++) {
                int kq = kq0 + u * 8;
                float4 v0 = st[u * 4 + 0], v1 = st[u * 4 + 1];
                float4 v2 = st[u * 4 + 2], v3 = st[u * 4 + 3];
                float a0[4] = {v0.x, v0.y, v0.z, v0.w};
                float a1[4] = {v1.x, v1.y, v1.z, v1.w};
                float a2[4] = {v2.x, v2.y, v2.z, v2.w};
                float a3[4] = {v3.x, v3.y, v3.z, v3.w};
#pragma unroll
                for (int j = 0; j < 4; j++) {
                    uint2 pr = make_uint2(bf2(a0[j], a1[j]), bf2(a2[j], a3[j]));
                    *(uint2*)(nb + b_off(4 * n4 + j, 8 * kq)) = pr;
                }
            }
        }
        __syncthreads();
    }

    // ---- epilogue: transpose to pixel-major bf16 via smem ----
    int g = lane >> 2;
    int t = lane & 3;
    __nv_bfloat16* T = (__nv_bfloat16*)(dyn + 32768);
#pragma unroll
    for (int mm = 0; mm < 2; mm++) {
        int row  = warpM * 32 + mm * 16 + g;
        float bias0 = bc[row];
        float bias8 = bc[row + 8];
#pragma unroll
        for (int nf = 0; nf < 4; nf++) {
            int ncol = warpN * 32 + nf * 8 + 2 * t;
            T[ncol * 68 + row]           = __float2bfloat16(acc[mm][nf][0] + bias0);
            T[(ncol + 1) * 68 + row]     = __float2bfloat16(acc[mm][nf][1] + bias0);
            T[ncol * 68 + row + 8]       = __float2bfloat16(acc[mm][nf][2] + bias8);
            T[(ncol + 1) * 68 + row + 8] = __float2bfloat16(acc[mm][nf][3] + bias8);
        }
    }
    __syncthreads();

    u32* gpx = (u32*)g_guide_px + ((size_t)b * HW + n0) * 32;
#pragma unroll
    for (int rr = 0; rr < 16; rr++) {
        int idx = tid + rr * 256;
        int n  = idx >> 5;
        int m2 = idx & 31;
        gpx[n * 32 + m2] = *(u32*)&T[n * 68 + 2 * m2];
    }
}

// ---------------------------------------------------------------------------
// Kernel 2 (HMMA, verified R10/R11): 3x3 conv + bias + softmax(25)
// ---------------------------------------------------------------------------
#define CV_AW_OFF 0
#define CV_HT_OFF 36864
#define CV_DS_OFF (36864 + 26112)
#define CV_DYN    (36864 + 26112 + 128 * 37 * 4)

__global__ void __launch_bounds__(256)
conv_softmax_mma_kernel(const float* __restrict__ we,
                        const float* __restrict__ be) {
    extern __shared__ char dyn[];
    char*  smAw = dyn + CV_AW_OFF;
    char*  smHt = dyn + CV_HT_OFF;
    float* smDs = (float*)(dyn + CV_DS_OFF);

    int tid = threadIdx.x;
    int wid = tid >> 5;
    int lane = tid & 31;
    int g = lane >> 2;
    int t = lane & 3;
    int b  = blockIdx.z;
    int x0 = blockIdx.x * 32;
    int y0 = blockIdx.y * 4;

    for (int i = tid; i < 9 * 32 * 32; i += 256) {
        int tap = i >> 10;
        int rem = i & 1023;
        int o  = rem >> 5;
        int cp = rem & 31;
        float w0 = 0.f, w1 = 0.f;
        if (o < KK) {
            w0 = we[(o * CC + 2 * cp) * 9 + tap];
            w1 = we[(o * CC + 2 * cp + 1) * 9 + tap];
        }
        *(u32*)(smAw + tap * 4096 + off128(o, cp * 4)) = bf2(w0, w1);
    }

    const u32* gpx = (const u32*)g_guide_px + (size_t)b * HW * 32;
    for (int i = tid; i < 204 * 32; i += 256) {
        int pos = i >> 5;
        int cp  = i & 31;
        int r   = pos / 34;
        int cxl = pos - r * 34;
        int gy = y0 + r - 1;
        int gx = x0 + cxl - 1;
        u32 v = 0u;
        if (gy >= 0 && gy < HH && gx >= 0 && gx < WW)
            v = gpx[(gy * WW + gx) * 32 + cp];
        *(u32*)(smHt + off128(pos, cp * 4)) = v;
    }
    __syncthreads();

    int nbase = wid * 16;
    float acc[2][2][4];
#pragma unroll
    for (int mm = 0; mm < 2; mm++)
#pragma unroll
        for (int nf = 0; nf < 2; nf++)
#pragma unroll
            for (int i = 0; i < 4; i++) acc[mm][nf][i] = 0.f;

#pragma unroll
    for (int tap = 0; tap < 9; tap++) {
        int ty = tap / 3, tx = tap - 3 * ty;
        const char* aw = smAw + tap * 4096;
#pragma unroll
        for (int ks = 0; ks < 4; ks++) {
            int kb0 = ks * 32 + 4 * t;
            int kb1 = kb0 + 16;
            u32 a[2][4];
#pragma unroll
            for (int mm = 0; mm < 2; mm++) {
                int row = mm * 16 + g;
                a[mm][0] = *(const u32*)(aw + off128(row,     kb0));
                a[mm][1] = *(const u32*)(aw + off128(row + 8, kb0));
                a[mm][2] = *(const u32*)(aw + off128(row,     kb1));
                a[mm][3] = *(const u32*)(aw + off128(row + 8, kb1));
            }
            u32 bf[2][2];
#pragma unroll
            for (int nf = 0; nf < 2; nf++) {
                int n = nbase + nf * 8 + g;
                int px = n & 31;
                int py = n >> 5;
                int pos = (py + ty) * 34 + (px + tx);
                bf[nf][0] = *(const u32*)(smHt + off128(pos, kb0));
                bf[nf][1] = *(const u32*)(smHt + off128(pos, kb1));
            }
#pragma unroll
            for (int mm = 0; mm < 2; mm++)
#pragma unroll
                for (int nf = 0; nf < 2; nf++)
                    mma_bf16(acc[mm][nf][0], acc[mm][nf][1],
                             acc[mm][nf][2], acc[mm][nf][3],
                             a[mm][0], a[mm][1], a[mm][2], a[mm][3],
                             bf[nf][0], bf[nf][1]);
        }
    }

#pragma unroll
    for (int mm = 0; mm < 2; mm++) {
        int row = mm * 16 + g;
#pragma unroll
        for (int nf = 0; nf < 2; nf++) {
            int n = nbase + nf * 8 + 2 * t;
            smDs[n * 37 + row]           = acc[mm][nf][0];
            smDs[(n + 1) * 37 + row]     = acc[mm][nf][1];
            smDs[n * 37 + row + 8]       = acc[mm][nf][2];
            smDs[(n + 1) * 37 + row + 8] = acc[mm][nf][3];
        }
    }
    __syncthreads();

    if (tid < 128) {
        int n = tid;
        int px = n & 31;
        int py = n >> 5;
        float a[KK];
        float m = -1e30f;
#pragma unroll
        for (int o = 0; o < KK; o++) {
            a[o] = smDs[n * 37 + o] + be[o];
            m = fmaxf(m, a[o]);
        }
        float s = 0.f;
#pragma unroll
        for (int o = 0; o < KK; o++) {
            a[o] = __expf(a[o] - m);
            s += a[o];
        }
        float inv = 1.f / s;
        float* mb = g_mask + (size_t)b * KK * HW + (y0 + py) * WW + (x0 + px);
#pragma unroll
        for (int o = 0; o < KK; o++) mb[(size_t)o * HW] = a[o] * inv;
    }
}

// ---------------------------------------------------------------------------
// Kernel 3 (v4, verified R11): CARAFE, double-buffered + pipelined.
// ---------------------------------------------------------------------------
#define CCH 8
#define CSPLIT 2
#define CPB (CP / CSPLIT)
#define NCHUNK (CPB / CCH)

__global__ void __launch_bounds__(256)
carafe_kernel(const float* __restrict__ pred,
              float* __restrict__ out) {
    __shared__ float ps[2][CCH][8][36];

    int zb = blockIdx.z;
    int b  = zb & (BB - 1);
    int cs = zb >> 2;
    int X0 = blockIdx.x * 64;
    int Y0 = blockIdx.y * 8;
    int lx = threadIdx.x & 31;
    int ly = threadIdx.x >> 5;
    int tid = threadIdx.x;
    int X = X0 + 2 * lx;
    int Y = Y0 + ly;

    ull m2[KK];
    const float* mb = g_mask + (size_t)b * KK * HW + Y * WW + X;
#pragma unroll
    for (int o = 0; o < KK; o++) {
        float2 mv = *(const float2*)&mb[(size_t)o * HW];
        m2[o] = pack2(mv.x, mv.y);
    }

    int py = ly >> 1;
    int px = lx;
    int yin0 = Y0 / 2 - 2;
    int xin0 = X0 / 2 - 2;

    int goff[9];
    int sch[9], sr[9], sc[9];
#pragma unroll
    for (int u = 0; u < 9; u++) {
        int i = u * 256 + tid;
        int ch = i / 288;
        int r  = (i / 36) % 8;
        int c  = i % 36;
        sch[u] = ch; sr[u] = r; sc[u] = c;
        goff[u] = ch * (PH * PW) + refl(yin0 + r, PH) * PW + refl(xin0 + c, PW);
    }

    const float* pb = pred + (size_t)b * CP * PH * PW + (size_t)cs * CPB * PH * PW;
    float* ob = out + (size_t)b * CP * HW + (size_t)cs * CPB * HW + Y * WW + X;

    {
        float r[9];
#pragma unroll
        for (int u = 0; u < 9; u++) r[u] = pb[goff[u]];
#pragma unroll
        for (int u = 0; u < 9; u++) ps[0][sch[u]][sr[u]][sc[u]] = r[u];
    }
    __syncthreads();

    float rnext[9];
    for (int c = 0; c < NCHUNK; c++) {
        if (c < NCHUNK - 1) {
            const float* pn = pb + (size_t)(c + 1) * CCH * PH * PW;
#pragma unroll
            for (int u = 0; u < 9; u++) rnext[u] = pn[goff[u]];
        }

        const float (*cur)[8][36] = ps[c & 1];
        int cp0 = c * CCH;
#pragma unroll
        for (int ch = 0; ch < CCH; ch++) {
            ull s2 = 0ULL;
#pragma unroll
            for (int i = 0; i < 5; i++)
#pragma unroll
                for (int j = 0; j < 5; j++) {
                    float p = cur[ch][py + i][px + j];
                    ffma2(s2, pack2(p, p), m2[i * 5 + j]);
                }
            float r0, r1;
            unpack2(s2, r0, r1);
            *(float2*)&ob[(size_t)(cp0 + ch) * HW] = make_float2(r0, r1);
        }

        if (c < NCHUNK - 1) {
#pragma unroll
            for (int u = 0; u < 9; u++)
                ps[(c + 1) & 1][sch[u]][sr[u]][sc[u]] = rnext[u];
        }
        __syncthreads();
    }
}

extern "C" void kernel_launch(void* const* d_in, const int* in_sizes, int n_in,
                              void* d_out, int out_size) {
    const float* pred = (const float*)d_in[0];
    const float* feat = (const float*)d_in[1];
    const float* wc   = (const float*)d_in[2];
    const float* bc   = (const float*)d_in[3];
    const float* we   = (const float*)d_in[4];
    const float* be   = (const float*)d_in[5];
    float* out = (float*)d_out;

    cudaFuncSetAttribute(compress_mma_kernel,
                         cudaFuncAttributeMaxDynamicSharedMemorySize, CMP_DYN);
    cudaFuncSetAttribute(conv_softmax_mma_kernel,
                         cudaFuncAttributeMaxDynamicSharedMemorySize, CV_DYN);

    compress_mma_kernel<<<dim3(HW / 128, BB), 256, CMP_DYN>>>(feat, wc, bc);
    conv_softmax_mma_kernel<<<dim3(WW / 32, HH / 4, BB), 256, CV_DYN>>>(we, be);
    carafe_kernel<<<dim3(WW / 64, HH / 8, BB * CSPLIT), 256>>>(pred, out);
}